// round 6
// baseline (speedup 1.0000x reference)
#include <cuda_runtime.h>
#include <math_constants.h>
#include <cstdint>

#define TRAJ        128
#define NNODES      1048576
#define NGRAPH      8192

__device__ float4 g_scratch[2 * NNODES];   // node i: [2i]={p.xyz, cum_dist}, [2i+1]={dr_.xyz, cum_msd}
__device__ float2 g_aux[NNODES];           // {cum_dist, cum_msd} compact copy for X-compose
__device__ float  g_cm[NNODES];            // local (within-graph) cummax of dr_norm
__device__ float  g_graphMax[NGRAPH];
__device__ float  g_fv[NGRAPH];            // dr_norm at first node of graph
__device__ float  g_gpfx[NGRAPH];          // exclusive global max prefix

// ---------------------------------------------------------------------------
// Kernel A: per-graph features. 2 graphs per 256-thread block.
// ---------------------------------------------------------------------------
__global__ void __launch_bounds__(256) kernelA(
    const float* __restrict__ P,
    float4* __restrict__ scr,
    float2* __restrict__ aux,
    float*  __restrict__ cmOut,
    float*  __restrict__ S,
    float*  __restrict__ U,
    float*  __restrict__ gMax,
    float*  __restrict__ gFv)
{
    const int tid  = threadIdx.x;
    const int half = tid >> 7;                 // which graph in this block
    const int t    = tid & 127;                // node within graph
    const int g    = blockIdx.x * 2 + half;
    const int lane = tid & 31;
    const int w    = tid >> 5;                 // 0..7
    const int wb   = half * 4;                 // first warp of this graph

    __shared__ float4 sP4[192];                // 2 graphs * 96 float4
    float* sP = (float*)sP4 + half * 384;
    __shared__ float red[8][9];
    __shared__ float wsum[8], wsum2[8], wmax[8];

    // coalesced load of both graphs' P tiles (768 floats = 192 float4)
    const float4* Pg = (const float4*)(P + (size_t)blockIdx.x * (2 * TRAJ * 3));
    if (tid < 192) sP4[tid] = Pg[tid];
    __syncthreads();

    float px = sP[3*t], py = sP[3*t+1], pz = sP[3*t+2];
    float dx = 0.f, dy = 0.f, dz = 0.f;
    if (t < TRAJ - 1) {
        dx = sP[3*t+3] - px;
        dy = sP[3*t+4] - py;
        dz = sP[3*t+5] - pz;
    }

    float v[9] = { px, py, pz, px*px, py*py, pz*pz, dx, dy, dz };
    #pragma unroll
    for (int k = 0; k < 9; k++) {
        #pragma unroll
        for (int off = 16; off; off >>= 1)
            v[k] += __shfl_xor_sync(0xffffffffu, v[k], off);
    }
    if (lane == 0) {
        #pragma unroll
        for (int k = 0; k < 9; k++) red[w][k] = v[k];
    }
    __syncthreads();
    float tot[9];
    #pragma unroll
    for (int k = 0; k < 9; k++)
        tot[k] = red[wb][k] + red[wb+1][k] + red[wb+2][k] + red[wb+3][k];

    const float invL = 1.0f / (float)TRAJ;
    float mx = tot[0]*invL, my = tot[1]*invL, mz = tot[2]*invL;
    float var = (tot[3]*invL - mx*mx) + (tot[4]*invL - my*my) + (tot[5]*invL - mz*mz);
    float pstd = sqrtf(var);
    float isf = 1.0f / pstd;

    float pnx = px*isf, pny = py*isf, pnz = pz*isf;
    float rdx = dx*isf, rdy = dy*isf, rdz = dz*isf;
    float dn  = sqrtf(1e-5f + rdx*rdx + rdy*rdy + rdz*rdz);
    float dn2 = dn * dn;

    float cs = dn, cs2 = dn2, cm = dn;
    #pragma unroll
    for (int off = 1; off < 32; off <<= 1) {
        float a  = __shfl_up_sync(0xffffffffu, cs,  off);
        float a2 = __shfl_up_sync(0xffffffffu, cs2, off);
        float am = __shfl_up_sync(0xffffffffu, cm,  off);
        if (lane >= off) { cs += a; cs2 += a2; cm = fmaxf(cm, am); }
    }
    if (lane == 31) { wsum[w] = cs; wsum2[w] = cs2; wmax[w] = cm; }
    __syncthreads();
    float o = 0.f, o2 = 0.f, om = -CUDART_INF_F;
    for (int j = wb; j < w; j++) { o += wsum[j]; o2 += wsum2[j]; om = fmaxf(om, wmax[j]); }
    cs += o; cs2 += o2; cm = fmaxf(cm, om);

    const int i = g * TRAJ + t;
    scr[2*i]     = make_float4(pnx, pny, pnz, cs);
    scr[2*i + 1] = make_float4(rdx, rdy, rdz, cs2);
    aux[i]   = make_float2(cs, cs2);
    cmOut[i] = cm;

    if (t == TRAJ - 1) gMax[g] = cm;
    if (t == 0) {
        gFv[g] = dn;
        S[2*g]     = pstd;
        S[2*g + 1] = (float)TRAJ;
        float ux = tot[6]*invL, uy = tot[7]*invL, uz = tot[8]*invL;
        float ui = 1.0f / sqrtf(1e-5f + ux*ux + uy*uy + uz*uz);
        U[3*g]     = ux * ui;
        U[3*g + 1] = uy * ui;
        U[3*g + 2] = uz * ui;
    }
}

// ---------------------------------------------------------------------------
// Kernel B: exclusive max-scan over 8192 graph maxima (pure prefix).
// ---------------------------------------------------------------------------
__global__ void __launch_bounds__(1024) kernelB(
    const float* __restrict__ gMax,
    float* __restrict__ out)
{
    const int t = threadIdx.x;
    const int lane = t & 31, w = t >> 5;
    const int CH = NGRAPH / 1024;   // 8

    float vals[8];
    float m = -CUDART_INF_F;
    #pragma unroll
    for (int j = 0; j < CH; j++) { vals[j] = gMax[t*CH + j]; m = fmaxf(m, vals[j]); }

    float x = m;
    #pragma unroll
    for (int off = 1; off < 32; off <<= 1) {
        float a = __shfl_up_sync(0xffffffffu, x, off);
        if (lane >= off) x = fmaxf(x, a);
    }
    float e_in_warp = __shfl_up_sync(0xffffffffu, x, 1);
    if (lane == 0) e_in_warp = -CUDART_INF_F;

    __shared__ float wm[32];
    __shared__ float wme[32];
    if (lane == 31) wm[w] = x;
    __syncthreads();
    if (w == 0) {
        float y = wm[lane];
        #pragma unroll
        for (int off = 1; off < 32; off <<= 1) {
            float a = __shfl_up_sync(0xffffffffu, y, off);
            if (lane >= off) y = fmaxf(y, a);
        }
        float ex = __shfl_up_sync(0xffffffffu, y, 1);
        if (lane == 0) ex = -CUDART_INF_F;
        wme[lane] = ex;
    }
    __syncthreads();

    float run = fmaxf(wme[w], e_in_warp);
    #pragma unroll
    for (int j = 0; j < CH; j++) {
        out[t*CH + j] = run;
        run = fmaxf(run, vals[j]);
    }
}

// ---------------------------------------------------------------------------
// Fused kernel C+D. Blocks [0, CBLK) compose X (256 nodes each); blocks
// [CBLK, CBLK+DBLK) compute edge features (512 edges each). The short
// DRAM-bound C work overlaps with the long L1-bound D work.
// ---------------------------------------------------------------------------
#define CBLK  (NNODES / 256)     // 4096

__global__ void __launch_bounds__(256) kernelCD(
    const float2* __restrict__ aux,
    const float*  __restrict__ cmIn,
    const float*  __restrict__ gpfx,
    const float*  __restrict__ gFv,
    float* __restrict__ X,
    const int* __restrict__ row,
    const int* __restrict__ col,
    const float4* __restrict__ scr,
    float* __restrict__ Eo,
    int Ecount)
{
    const int t = threadIdx.x;

    if (blockIdx.x < CBLK) {
        // ---- C part: compose X ----
        const int i = blockIdx.x * 256 + t;
        const int g = i >> 7;
        float cm  = cmIn[i];
        float gp  = __ldg(gpfx + g);
        float fv  = __ldg(gFv + g);
        float2 ab = __ldg(aux + i);
        float4 xo = make_float4((float)((i & (TRAJ-1)) + 1) * (1.0f / (float)TRAJ),
                                ab.x, ab.y, fmaxf(cm, gp) + fv);
        __stcs(((float4*)X) + i, xo);
        return;
    }

    // ---- D part: edge features ----
    __shared__ __align__(16) float sm[512 * 5];
    const int warp = t >> 5;
    const int lane = t & 31;
    const int k = lane >> 1;             // pair index 0..15
    const int h = lane & 1;              // half selector
    const int base = (blockIdx.x - CBLK) * 512;
    const bool full = (base + 512 <= Ecount);

    if (full) {
        // Stage 1: prefetch all indices (MLP=8)
        int rr[4], cc[4];
        #pragma unroll
        for (int p = 0; p < 4; p++) {
            const int e = base + warp * 64 + p * 16 + k;
            rr[p] = __ldcs(row + e);
            cc[p] = __ldcs(col + e);
        }
        // Stage 2: issue all endpoint gathers (MLP=8 x 16B).
        // Lanes 2k,2k+1 hit adjacent float4s of one endpoint's 128B line in
        // the same instruction -> one L1 wavefront per endpoint.
        float4 Ar[4], Ac[4];
        #pragma unroll
        for (int p = 0; p < 4; p++) {
            Ar[p] = __ldg(scr + 2*rr[p] + h);
            Ac[p] = __ldg(scr + 2*cc[p] + h);
        }
        // Stage 3: compute + stage to smem
        #pragma unroll
        for (int p = 0; p < 4; p++) {
            const int eb = warp * 64 + p * 16 + k;
            float fb = Ar[p].w - Ac[p].w;   // h=0: d_cum_dist, h=1: d_cum_msd
            if (h == 0) {
                float ddx = Ar[p].x - Ac[p].x, ddy = Ar[p].y - Ac[p].y, ddz = Ar[p].z - Ac[p].z;
                sm[eb*5 + 0] = (float)((rr[p] & (TRAJ-1)) - (cc[p] & (TRAJ-1))) * (1.0f / (float)TRAJ);
                sm[eb*5 + 1] = sqrtf(ddx*ddx + ddy*ddy + ddz*ddz);     // d
                sm[eb*5 + 3] = fb;
            } else {
                sm[eb*5 + 2] = Ar[p].x*Ac[p].x + Ar[p].y*Ac[p].y + Ar[p].z*Ac[p].z;  // corr
                sm[eb*5 + 4] = fb;
            }
        }
        __syncthreads();

        if (t == 0) {
            asm volatile("fence.proxy.async.shared::cta;" ::: "memory");
            unsigned int s_sm = (unsigned int)__cvta_generic_to_shared(sm);
            asm volatile(
                "cp.async.bulk.global.shared::cta.bulk_group [%0], [%1], %2;"
                :: "l"(Eo + (size_t)base * 5), "r"(s_sm), "r"(10240u)
                : "memory");
            asm volatile("cp.async.bulk.commit_group;" ::: "memory");
            asm volatile("cp.async.bulk.wait_group 0;" ::: "memory");
        }
    } else {
        // tail fallback (not hit for E = 8,388,608)
        #pragma unroll
        for (int p = 0; p < 4; p++) {
            const int eb = warp * 64 + p * 16 + k;
            const int e  = base + eb;
            float fa = 0.f, fb = 0.f, f0 = 0.f;
            if (e < Ecount) {
                const int r = __ldcs(row + e);
                const int c = __ldcs(col + e);
                float4 Ar = __ldg(scr + 2*r + h);
                float4 Ac = __ldg(scr + 2*c + h);
                if (h == 0) {
                    float ddx = Ar.x - Ac.x, ddy = Ar.y - Ac.y, ddz = Ar.z - Ac.z;
                    fa = sqrtf(ddx*ddx + ddy*ddy + ddz*ddz);
                } else {
                    fa = Ar.x*Ac.x + Ar.y*Ac.y + Ar.z*Ac.z;
                }
                fb = Ar.w - Ac.w;
                f0 = (float)((r & (TRAJ-1)) - (c & (TRAJ-1))) * (1.0f / (float)TRAJ);
            }
            if (h == 0) {
                sm[eb*5 + 0] = f0;
                sm[eb*5 + 1] = fa;
                sm[eb*5 + 3] = fb;
            } else {
                sm[eb*5 + 2] = fa;
                sm[eb*5 + 4] = fb;
            }
        }
        __syncthreads();
        const int nvalid = Ecount - base;
        if (nvalid > 0) {
            const int nf = nvalid * 5;
            for (int j = t; j < nf; j += 256) __stcs(Eo + (size_t)base * 5 + j, sm[j]);
        }
    }
}

// ---------------------------------------------------------------------------
extern "C" void kernel_launch(void* const* d_in, const int* in_sizes, int n_in,
                              void* d_out, int out_size)
{
    const float* P   = (const float*)d_in[0];
    const int*   row = (const int*)d_in[2];
    const int*   col = (const int*)d_in[3];

    const int N = in_sizes[0] / 3;
    const int G = N / TRAJ;
    const int E = in_sizes[2];

    float* out = (float*)d_out;
    float* X  = out;                       // [N,4]
    float* Eo = out + (size_t)4 * N;       // [E,5]
    float* S  = Eo + (size_t)5 * E;        // [G,2]
    float* U  = S + (size_t)2 * G;         // [G,3]

    float4* scr;  cudaGetSymbolAddress((void**)&scr,  g_scratch);
    float2* aux;  cudaGetSymbolAddress((void**)&aux,  g_aux);
    float*  cm;   cudaGetSymbolAddress((void**)&cm,   g_cm);
    float*  gMax; cudaGetSymbolAddress((void**)&gMax, g_graphMax);
    float*  gFv;  cudaGetSymbolAddress((void**)&gFv,  g_fv);
    float*  gPfx; cudaGetSymbolAddress((void**)&gPfx, g_gpfx);

    const int dblk = (E + 511) / 512;

    kernelA<<<G / 2, 256>>>(P, scr, aux, cm, S, U, gMax, gFv);
    kernelB<<<1, 1024>>>(gMax, gPfx);
    kernelCD<<<CBLK + dblk, 256>>>(aux, cm, gPfx, gFv, X, row, col, scr, Eo, E);
}

// round 7
// speedup vs baseline: 1.8508x; 1.8508x over previous
#include <cuda_runtime.h>
#include <math_constants.h>
#include <cstdint>

#define TRAJ        128
#define NNODES      1048576
#define NGRAPH      8192

__device__ float4 g_scratch[2 * NNODES];   // node i: [2i]={p.xyz, cum_dist}, [2i+1]={dr_.xyz, cum_msd}
__device__ float2 g_aux[NNODES];           // {cum_dist, cum_msd} compact copy for X-compose
__device__ float  g_cm[NNODES];            // local (within-graph) cummax of dr_norm
__device__ float  g_graphMax[NGRAPH];
__device__ float  g_fv[NGRAPH];            // dr_norm at first node of graph
__device__ float  g_gpfx[NGRAPH];          // exclusive global max prefix

// ---------------------------------------------------------------------------
// Kernel A: per-graph features. 1 block (128 thr) per graph.  (R5 version)
// ---------------------------------------------------------------------------
__global__ void __launch_bounds__(128) kernelA(
    const float* __restrict__ P,
    float4* __restrict__ scr,
    float2* __restrict__ aux,
    float*  __restrict__ cmOut,
    float*  __restrict__ S,
    float*  __restrict__ U,
    float*  __restrict__ gMax,
    float*  __restrict__ gFv)
{
    const int g = blockIdx.x;
    const int t = threadIdx.x;
    const int lane = t & 31;
    const int w = t >> 5;

    __shared__ float4 sP4[96];
    float* sP = (float*)sP4;
    __shared__ float red[4][9];
    __shared__ float wsum[4], wsum2[4], wmax[4];

    const float4* Pg = (const float4*)(P + (size_t)g * (TRAJ * 3));
    if (t < 96) sP4[t] = Pg[t];
    __syncthreads();

    float px = sP[3*t], py = sP[3*t+1], pz = sP[3*t+2];
    float dx = 0.f, dy = 0.f, dz = 0.f;
    if (t < TRAJ - 1) {
        dx = sP[3*t+3] - px;
        dy = sP[3*t+4] - py;
        dz = sP[3*t+5] - pz;
    }

    float v[9] = { px, py, pz, px*px, py*py, pz*pz, dx, dy, dz };
    #pragma unroll
    for (int k = 0; k < 9; k++) {
        #pragma unroll
        for (int off = 16; off; off >>= 1)
            v[k] += __shfl_xor_sync(0xffffffffu, v[k], off);
    }
    if (lane == 0) {
        #pragma unroll
        for (int k = 0; k < 9; k++) red[w][k] = v[k];
    }
    __syncthreads();
    float tot[9];
    #pragma unroll
    for (int k = 0; k < 9; k++)
        tot[k] = red[0][k] + red[1][k] + red[2][k] + red[3][k];

    const float invL = 1.0f / (float)TRAJ;
    float mx = tot[0]*invL, my = tot[1]*invL, mz = tot[2]*invL;
    float var = (tot[3]*invL - mx*mx) + (tot[4]*invL - my*my) + (tot[5]*invL - mz*mz);
    float pstd = sqrtf(var);
    float isf = 1.0f / pstd;

    float pnx = px*isf, pny = py*isf, pnz = pz*isf;
    float rdx = dx*isf, rdy = dy*isf, rdz = dz*isf;
    float dn  = sqrtf(1e-5f + rdx*rdx + rdy*rdy + rdz*rdz);
    float dn2 = dn * dn;

    float cs = dn, cs2 = dn2, cm = dn;
    #pragma unroll
    for (int off = 1; off < 32; off <<= 1) {
        float a  = __shfl_up_sync(0xffffffffu, cs,  off);
        float a2 = __shfl_up_sync(0xffffffffu, cs2, off);
        float am = __shfl_up_sync(0xffffffffu, cm,  off);
        if (lane >= off) { cs += a; cs2 += a2; cm = fmaxf(cm, am); }
    }
    if (lane == 31) { wsum[w] = cs; wsum2[w] = cs2; wmax[w] = cm; }
    __syncthreads();
    float o = 0.f, o2 = 0.f, om = -CUDART_INF_F;
    for (int j = 0; j < w; j++) { o += wsum[j]; o2 += wsum2[j]; om = fmaxf(om, wmax[j]); }
    cs += o; cs2 += o2; cm = fmaxf(cm, om);

    const int i = g * TRAJ + t;
    scr[2*i]     = make_float4(pnx, pny, pnz, cs);
    scr[2*i + 1] = make_float4(rdx, rdy, rdz, cs2);
    aux[i]   = make_float2(cs, cs2);
    cmOut[i] = cm;

    if (t == TRAJ - 1) gMax[g] = cm;
    if (t == 0) {
        gFv[g] = dn;
        S[2*g]     = pstd;
        S[2*g + 1] = (float)TRAJ;
        float ux = tot[6]*invL, uy = tot[7]*invL, uz = tot[8]*invL;
        float ui = 1.0f / sqrtf(1e-5f + ux*ux + uy*uy + uz*uz);
        U[3*g]     = ux * ui;
        U[3*g + 1] = uy * ui;
        U[3*g + 2] = uz * ui;
    }
}

// ---------------------------------------------------------------------------
// Kernel B: exclusive max-scan over 8192 graph maxima (pure prefix).
// ---------------------------------------------------------------------------
__global__ void __launch_bounds__(1024) kernelB(
    const float* __restrict__ gMax,
    float* __restrict__ out)
{
    const int t = threadIdx.x;
    const int lane = t & 31, w = t >> 5;
    const int CH = NGRAPH / 1024;   // 8

    float vals[8];
    float m = -CUDART_INF_F;
    #pragma unroll
    for (int j = 0; j < CH; j++) { vals[j] = gMax[t*CH + j]; m = fmaxf(m, vals[j]); }

    float x = m;
    #pragma unroll
    for (int off = 1; off < 32; off <<= 1) {
        float a = __shfl_up_sync(0xffffffffu, x, off);
        if (lane >= off) x = fmaxf(x, a);
    }
    float e_in_warp = __shfl_up_sync(0xffffffffu, x, 1);
    if (lane == 0) e_in_warp = -CUDART_INF_F;

    __shared__ float wm[32];
    __shared__ float wme[32];
    if (lane == 31) wm[w] = x;
    __syncthreads();
    if (w == 0) {
        float y = wm[lane];
        #pragma unroll
        for (int off = 1; off < 32; off <<= 1) {
            float a = __shfl_up_sync(0xffffffffu, y, off);
            if (lane >= off) y = fmaxf(y, a);
        }
        float ex = __shfl_up_sync(0xffffffffu, y, 1);
        if (lane == 0) ex = -CUDART_INF_F;
        wme[lane] = ex;
    }
    __syncthreads();

    float run = fmaxf(wme[w], e_in_warp);
    #pragma unroll
    for (int j = 0; j < CH; j++) {
        out[t*CH + j] = run;
        run = fmaxf(run, vals[j]);
    }
}

// ---------------------------------------------------------------------------
// Fused kernel D+C. D blocks FIRST (the long pole starts immediately);
// the trailing CBLK blocks compose X and drain inside D's tail wave.
// D body is the proven R5 version (interleaved passes, no front-batching).
// ---------------------------------------------------------------------------
__global__ void __launch_bounds__(256, 4) kernelDC(
    const int* __restrict__ row,
    const int* __restrict__ col,
    const float4* __restrict__ scr,
    float* __restrict__ Eo,
    int Ecount, int dblk,
    const float2* __restrict__ aux,
    const float*  __restrict__ cmIn,
    const float*  __restrict__ gpfx,
    const float*  __restrict__ gFv,
    float* __restrict__ X)
{
    const int t = threadIdx.x;

    if (blockIdx.x >= (unsigned)dblk) {
        // ---- C part: compose X (256 nodes per block) ----
        const int i = (blockIdx.x - dblk) * 256 + t;
        const int g = i >> 7;
        float cm  = cmIn[i];
        float gp  = __ldg(gpfx + g);
        float fv  = __ldg(gFv + g);
        float2 ab = __ldg(aux + i);
        float4 xo = make_float4((float)((i & (TRAJ-1)) + 1) * (1.0f / (float)TRAJ),
                                ab.x, ab.y, fmaxf(cm, gp) + fv);
        __stcs(((float4*)X) + i, xo);
        return;
    }

    // ---- D part: edge features (R5 body) ----
    __shared__ __align__(16) float sm[512 * 5];
    const int warp = t >> 5;
    const int lane = t & 31;
    const int k = lane >> 1;             // pair index 0..15
    const int h = lane & 1;              // half selector
    const int base = blockIdx.x * 512;
    const bool full = (base + 512 <= Ecount);

    if (full) {
        #pragma unroll
        for (int pass = 0; pass < 4; pass++) {
            const int eb = warp * 64 + pass * 16 + k;
            const int e  = base + eb;
            const int r = __ldcs(row + e);
            const int c = __ldcs(col + e);
            // lanes 2k,2k+1 hit adjacent float4s of one endpoint's 128B line
            // in the same instruction -> one wavefront per endpoint.
            float4 Ar = __ldg(scr + 2*r + h);
            float4 Ac = __ldg(scr + 2*c + h);
            float fa, fb = Ar.w - Ac.w;   // h=0: d_cum_dist, h=1: d_cum_msd
            if (h == 0) {
                float ddx = Ar.x - Ac.x, ddy = Ar.y - Ac.y, ddz = Ar.z - Ac.z;
                fa = sqrtf(ddx*ddx + ddy*ddy + ddz*ddz);          // d
                sm[eb*5 + 0] = (float)((r & (TRAJ-1)) - (c & (TRAJ-1))) * (1.0f / (float)TRAJ);
                sm[eb*5 + 1] = fa;
                sm[eb*5 + 3] = fb;
            } else {
                fa = Ar.x*Ac.x + Ar.y*Ac.y + Ar.z*Ac.z;           // corr
                sm[eb*5 + 2] = fa;
                sm[eb*5 + 4] = fb;
            }
        }
        __syncthreads();

        if (t == 0) {
            // order generic-proxy STS before async-proxy TMA read of smem
            asm volatile("fence.proxy.async.shared::cta;" ::: "memory");
            unsigned int s_sm = (unsigned int)__cvta_generic_to_shared(sm);
            asm volatile(
                "cp.async.bulk.global.shared::cta.bulk_group [%0], [%1], %2;"
                :: "l"(Eo + (size_t)base * 5), "r"(s_sm), "r"(10240u)
                : "memory");
            asm volatile("cp.async.bulk.commit_group;" ::: "memory");
            asm volatile("cp.async.bulk.wait_group 0;" ::: "memory");
        }
    } else {
        // tail fallback (not hit for E = 8,388,608, kept for generality)
        #pragma unroll
        for (int pass = 0; pass < 4; pass++) {
            const int eb = warp * 64 + pass * 16 + k;
            const int e  = base + eb;
            float fa = 0.f, fb = 0.f, f0 = 0.f;
            if (e < Ecount) {
                const int r = __ldcs(row + e);
                const int c = __ldcs(col + e);
                float4 Ar = __ldg(scr + 2*r + h);
                float4 Ac = __ldg(scr + 2*c + h);
                if (h == 0) {
                    float ddx = Ar.x - Ac.x, ddy = Ar.y - Ac.y, ddz = Ar.z - Ac.z;
                    fa = sqrtf(ddx*ddx + ddy*ddy + ddz*ddz);
                } else {
                    fa = Ar.x*Ac.x + Ar.y*Ac.y + Ar.z*Ac.z;
                }
                fb = Ar.w - Ac.w;
                f0 = (float)((r & (TRAJ-1)) - (c & (TRAJ-1))) * (1.0f / (float)TRAJ);
            }
            if (h == 0) {
                sm[eb*5 + 0] = f0;
                sm[eb*5 + 1] = fa;
                sm[eb*5 + 3] = fb;
            } else {
                sm[eb*5 + 2] = fa;
                sm[eb*5 + 4] = fb;
            }
        }
        __syncthreads();
        const int nvalid = Ecount - base;
        if (nvalid > 0) {
            const int nf = nvalid * 5;
            for (int j = t; j < nf; j += 256) __stcs(Eo + (size_t)base * 5 + j, sm[j]);
        }
    }
}

// ---------------------------------------------------------------------------
extern "C" void kernel_launch(void* const* d_in, const int* in_sizes, int n_in,
                              void* d_out, int out_size)
{
    const float* P   = (const float*)d_in[0];
    const int*   row = (const int*)d_in[2];
    const int*   col = (const int*)d_in[3];

    const int N = in_sizes[0] / 3;
    const int G = N / TRAJ;
    const int E = in_sizes[2];

    float* out = (float*)d_out;
    float* X  = out;                       // [N,4]
    float* Eo = out + (size_t)4 * N;       // [E,5]
    float* S  = Eo + (size_t)5 * E;        // [G,2]
    float* U  = S + (size_t)2 * G;         // [G,3]

    float4* scr;  cudaGetSymbolAddress((void**)&scr,  g_scratch);
    float2* aux;  cudaGetSymbolAddress((void**)&aux,  g_aux);
    float*  cm;   cudaGetSymbolAddress((void**)&cm,   g_cm);
    float*  gMax; cudaGetSymbolAddress((void**)&gMax, g_graphMax);
    float*  gFv;  cudaGetSymbolAddress((void**)&gFv,  g_fv);
    float*  gPfx; cudaGetSymbolAddress((void**)&gPfx, g_gpfx);

    const int dblk = (E + 511) / 512;
    const int cblk = N / 256;

    kernelA<<<G, 128>>>(P, scr, aux, cm, S, U, gMax, gFv);
    kernelB<<<1, 1024>>>(gMax, gPfx);
    kernelDC<<<dblk + cblk, 256>>>(row, col, scr, Eo, E, dblk,
                                   aux, cm, gPfx, gFv, X);
}

// round 8
// speedup vs baseline: 1.9141x; 1.0342x over previous
#include <cuda_runtime.h>
#include <math_constants.h>
#include <cstdint>

#define TRAJ        128
#define NNODES      1048576
#define NGRAPH      8192

__device__ float4 g_scratch[2 * NNODES];   // node i: [2i]={p.xyz, cum_dist}, [2i+1]={dr_.xyz, cum_msd}
__device__ float2 g_aux[NNODES];           // {cum_dist, cum_msd} compact copy for X-compose
__device__ float  g_cm[NNODES];            // local (within-graph) cummax of dr_norm
__device__ float  g_graphMax[NGRAPH];
__device__ float  g_fv[NGRAPH];            // dr_norm at first node of graph
__device__ float  g_gpfx[NGRAPH];          // exclusive global max prefix

// ---------------------------------------------------------------------------
// Kernel A: per-graph features. 1 block (128 thr) per graph.
// Slimmed: 4-value reduction (Sum p, Sum |p|^2) + telescoped Sum dr.
// ---------------------------------------------------------------------------
__global__ void __launch_bounds__(128) kernelA(
    const float* __restrict__ P,
    float4* __restrict__ scr,
    float2* __restrict__ aux,
    float*  __restrict__ cmOut,
    float*  __restrict__ S,
    float*  __restrict__ U,
    float*  __restrict__ gMax,
    float*  __restrict__ gFv)
{
    const int g = blockIdx.x;
    const int t = threadIdx.x;
    const int lane = t & 31;
    const int w = t >> 5;

    __shared__ float4 sP4[96];
    float* sP = (float*)sP4;
    __shared__ float red[4][4];
    __shared__ float wsum[4], wsum2[4], wmax[4];

    const float4* Pg = (const float4*)(P + (size_t)g * (TRAJ * 3));
    if (t < 96) sP4[t] = Pg[t];
    __syncthreads();

    float px = sP[3*t], py = sP[3*t+1], pz = sP[3*t+2];
    float dx = 0.f, dy = 0.f, dz = 0.f;
    if (t < TRAJ - 1) {
        dx = sP[3*t+3] - px;
        dy = sP[3*t+4] - py;
        dz = sP[3*t+5] - pz;
    }

    // 4-value block reduction: sum P (3) + sum |P|^2 (1)
    float v[4] = { px, py, pz, px*px + py*py + pz*pz };
    #pragma unroll
    for (int k = 0; k < 4; k++) {
        #pragma unroll
        for (int off = 16; off; off >>= 1)
            v[k] += __shfl_xor_sync(0xffffffffu, v[k], off);
    }
    if (lane == 0) {
        #pragma unroll
        for (int k = 0; k < 4; k++) red[w][k] = v[k];
    }
    __syncthreads();
    float tot[4];
    #pragma unroll
    for (int k = 0; k < 4; k++)
        tot[k] = red[0][k] + red[1][k] + red[2][k] + red[3][k];

    const float invL = 1.0f / (float)TRAJ;
    float mx = tot[0]*invL, my = tot[1]*invL, mz = tot[2]*invL;
    // sum_d Var_d = E[|p|^2] - |mean|^2
    float var = tot[3]*invL - (mx*mx + my*my + mz*mz);
    float pstd = sqrtf(var);
    float isf = 1.0f / pstd;

    float pnx = px*isf, pny = py*isf, pnz = pz*isf;
    float rdx = dx*isf, rdy = dy*isf, rdz = dz*isf;
    float dn  = sqrtf(1e-5f + rdx*rdx + rdy*rdy + rdz*rdz);
    float dn2 = dn * dn;

    float cs = dn, cs2 = dn2, cm = dn;
    #pragma unroll
    for (int off = 1; off < 32; off <<= 1) {
        float a  = __shfl_up_sync(0xffffffffu, cs,  off);
        float a2 = __shfl_up_sync(0xffffffffu, cs2, off);
        float am = __shfl_up_sync(0xffffffffu, cm,  off);
        if (lane >= off) { cs += a; cs2 += a2; cm = fmaxf(cm, am); }
    }
    if (lane == 31) { wsum[w] = cs; wsum2[w] = cs2; wmax[w] = cm; }
    __syncthreads();
    float o = 0.f, o2 = 0.f, om = -CUDART_INF_F;
    for (int j = 0; j < w; j++) { o += wsum[j]; o2 += wsum2[j]; om = fmaxf(om, wmax[j]); }
    cs += o; cs2 += o2; cm = fmaxf(cm, om);

    const int i = g * TRAJ + t;
    scr[2*i]     = make_float4(pnx, pny, pnz, cs);
    scr[2*i + 1] = make_float4(rdx, rdy, rdz, cs2);
    aux[i]   = make_float2(cs, cs2);
    cmOut[i] = cm;

    if (t == TRAJ - 1) gMax[g] = cm;
    if (t == 0) {
        gFv[g] = dn;
        S[2*g]     = pstd;
        S[2*g + 1] = (float)TRAJ;
        // telescoped mean jump: sum dr = P[last] - P[first]  (fill_last => exact)
        float ux = (sP[381] - sP[0]) * invL;
        float uy = (sP[382] - sP[1]) * invL;
        float uz = (sP[383] - sP[2]) * invL;
        float ui = 1.0f / sqrtf(1e-5f + ux*ux + uy*uy + uz*uz);
        U[3*g]     = ux * ui;
        U[3*g + 1] = uy * ui;
        U[3*g + 2] = uz * ui;
    }
}

// ---------------------------------------------------------------------------
// Kernel B: exclusive max-scan over 8192 graph maxima (pure prefix).
// ---------------------------------------------------------------------------
__global__ void __launch_bounds__(1024) kernelB(
    const float* __restrict__ gMax,
    float* __restrict__ out)
{
    const int t = threadIdx.x;
    const int lane = t & 31, w = t >> 5;
    const int CH = NGRAPH / 1024;   // 8

    float vals[8];
    float m = -CUDART_INF_F;
    #pragma unroll
    for (int j = 0; j < CH; j++) { vals[j] = gMax[t*CH + j]; m = fmaxf(m, vals[j]); }

    float x = m;
    #pragma unroll
    for (int off = 1; off < 32; off <<= 1) {
        float a = __shfl_up_sync(0xffffffffu, x, off);
        if (lane >= off) x = fmaxf(x, a);
    }
    float e_in_warp = __shfl_up_sync(0xffffffffu, x, 1);
    if (lane == 0) e_in_warp = -CUDART_INF_F;

    __shared__ float wm[32];
    __shared__ float wme[32];
    if (lane == 31) wm[w] = x;
    __syncthreads();
    if (w == 0) {
        float y = wm[lane];
        #pragma unroll
        for (int off = 1; off < 32; off <<= 1) {
            float a = __shfl_up_sync(0xffffffffu, y, off);
            if (lane >= off) y = fmaxf(y, a);
        }
        float ex = __shfl_up_sync(0xffffffffu, y, 1);
        if (lane == 0) ex = -CUDART_INF_F;
        wme[lane] = ex;
    }
    __syncthreads();

    float run = fmaxf(wme[w], e_in_warp);
    #pragma unroll
    for (int j = 0; j < CH; j++) {
        out[t*CH + j] = run;
        run = fmaxf(run, vals[j]);
    }
}

// ---------------------------------------------------------------------------
// Fused kernel D+C. D blocks FIRST; trailing blocks compose X in D's tail.
// ---------------------------------------------------------------------------
__global__ void __launch_bounds__(256, 4) kernelDC(
    const int* __restrict__ row,
    const int* __restrict__ col,
    const float4* __restrict__ scr,
    float* __restrict__ Eo,
    int Ecount, int dblk,
    const float2* __restrict__ aux,
    const float*  __restrict__ cmIn,
    const float*  __restrict__ gpfx,
    const float*  __restrict__ gFv,
    float* __restrict__ X)
{
    const int t = threadIdx.x;

    if (blockIdx.x >= (unsigned)dblk) {
        // ---- C part: compose X (256 nodes per block) ----
        const int i = (blockIdx.x - dblk) * 256 + t;
        const int g = i >> 7;
        float cm  = cmIn[i];
        float gp  = __ldg(gpfx + g);
        float fv  = __ldg(gFv + g);
        float2 ab = __ldg(aux + i);
        float4 xo = make_float4((float)((i & (TRAJ-1)) + 1) * (1.0f / (float)TRAJ),
                                ab.x, ab.y, fmaxf(cm, gp) + fv);
        __stcs(((float4*)X) + i, xo);
        return;
    }

    // ---- D part: edge features ----
    __shared__ __align__(16) float sm[512 * 5];
    const int warp = t >> 5;
    const int lane = t & 31;
    const int k = lane >> 1;             // pair index 0..15
    const int h = lane & 1;              // half selector
    const int base = blockIdx.x * 512;
    const bool full = (base + 512 <= Ecount);

    if (full) {
        #pragma unroll
        for (int pass = 0; pass < 4; pass++) {
            const int eb = warp * 64 + pass * 16 + k;
            const int e  = base + eb;
            const int r = __ldcs(row + e);
            const int c = __ldcs(col + e);
            // lanes 2k,2k+1 hit adjacent float4s of one endpoint's 128B line
            // in the same instruction -> one wavefront per endpoint.
            float4 Ar = __ldg(scr + 2*r + h);
            float4 Ac = __ldg(scr + 2*c + h);
            float fa, fb = Ar.w - Ac.w;   // h=0: d_cum_dist, h=1: d_cum_msd
            if (h == 0) {
                float ddx = Ar.x - Ac.x, ddy = Ar.y - Ac.y, ddz = Ar.z - Ac.z;
                fa = sqrtf(ddx*ddx + ddy*ddy + ddz*ddz);          // d
                sm[eb*5 + 0] = (float)((r & (TRAJ-1)) - (c & (TRAJ-1))) * (1.0f / (float)TRAJ);
                sm[eb*5 + 1] = fa;
                sm[eb*5 + 3] = fb;
            } else {
                fa = Ar.x*Ac.x + Ar.y*Ac.y + Ar.z*Ac.z;           // corr
                sm[eb*5 + 2] = fa;
                sm[eb*5 + 4] = fb;
            }
        }
        __syncthreads();

        if (t == 0) {
            // order generic-proxy STS before async-proxy TMA read of smem
            asm volatile("fence.proxy.async.shared::cta;" ::: "memory");
            unsigned int s_sm = (unsigned int)__cvta_generic_to_shared(sm);
            asm volatile(
                "cp.async.bulk.global.shared::cta.bulk_group [%0], [%1], %2;"
                :: "l"(Eo + (size_t)base * 5), "r"(s_sm), "r"(10240u)
                : "memory");
            asm volatile("cp.async.bulk.commit_group;" ::: "memory");
            asm volatile("cp.async.bulk.wait_group 0;" ::: "memory");
        }
    } else {
        // tail fallback (not hit for E = 8,388,608, kept for generality)
        #pragma unroll
        for (int pass = 0; pass < 4; pass++) {
            const int eb = warp * 64 + pass * 16 + k;
            const int e  = base + eb;
            float fa = 0.f, fb = 0.f, f0 = 0.f;
            if (e < Ecount) {
                const int r = __ldcs(row + e);
                const int c = __ldcs(col + e);
                float4 Ar = __ldg(scr + 2*r + h);
                float4 Ac = __ldg(scr + 2*c + h);
                if (h == 0) {
                    float ddx = Ar.x - Ac.x, ddy = Ar.y - Ac.y, ddz = Ar.z - Ac.z;
                    fa = sqrtf(ddx*ddx + ddy*ddy + ddz*ddz);
                } else {
                    fa = Ar.x*Ac.x + Ar.y*Ac.y + Ar.z*Ac.z;
                }
                fb = Ar.w - Ac.w;
                f0 = (float)((r & (TRAJ-1)) - (c & (TRAJ-1))) * (1.0f / (float)TRAJ);
            }
            if (h == 0) {
                sm[eb*5 + 0] = f0;
                sm[eb*5 + 1] = fa;
                sm[eb*5 + 3] = fb;
            } else {
                sm[eb*5 + 2] = fa;
                sm[eb*5 + 4] = fb;
            }
        }
        __syncthreads();
        const int nvalid = Ecount - base;
        if (nvalid > 0) {
            const int nf = nvalid * 5;
            for (int j = t; j < nf; j += 256) __stcs(Eo + (size_t)base * 5 + j, sm[j]);
        }
    }
}

// ---------------------------------------------------------------------------
extern "C" void kernel_launch(void* const* d_in, const int* in_sizes, int n_in,
                              void* d_out, int out_size)
{
    const float* P   = (const float*)d_in[0];
    const int*   row = (const int*)d_in[2];
    const int*   col = (const int*)d_in[3];

    const int N = in_sizes[0] / 3;
    const int G = N / TRAJ;
    const int E = in_sizes[2];

    float* out = (float*)d_out;
    float* X  = out;                       // [N,4]
    float* Eo = out + (size_t)4 * N;       // [E,5]
    float* S  = Eo + (size_t)5 * E;        // [G,2]
    float* U  = S + (size_t)2 * G;         // [G,3]

    float4* scr;  cudaGetSymbolAddress((void**)&scr,  g_scratch);
    float2* aux;  cudaGetSymbolAddress((void**)&aux,  g_aux);
    float*  cm;   cudaGetSymbolAddress((void**)&cm,   g_cm);
    float*  gMax; cudaGetSymbolAddress((void**)&gMax, g_graphMax);
    float*  gFv;  cudaGetSymbolAddress((void**)&gFv,  g_fv);
    float*  gPfx; cudaGetSymbolAddress((void**)&gPfx, g_gpfx);

    const int dblk = (E + 511) / 512;
    const int cblk = N / 256;

    kernelA<<<G, 128>>>(P, scr, aux, cm, S, U, gMax, gFv);
    kernelB<<<1, 1024>>>(gMax, gPfx);
    kernelDC<<<dblk + cblk, 256>>>(row, col, scr, Eo, E, dblk,
                                   aux, cm, gPfx, gFv, X);
}